// round 10
// baseline (speedup 1.0000x reference)
#include <cuda_runtime.h>
#include <cuda_fp8.h>
#include <cuda_fp16.h>
#include <cstdint>

// Quantize_55327768707293
// x: [8192, 8192] fp32. Tiled 128x128. Per tile:
//   absmax -> e = ceil(log2(absmax)) (absmax==0 -> e=0)
//   scale = 2^(e-1)   (MAX_EXP = 1)
//   xq = fp32(fp8_e5m2(x * 2^(1-e)))
// Output: [xq (8192*8192 fp32) | scale (64*64 fp32)]
//
// R10: R9 (best: 4096 CTAs, 512 thr, 2 CTAs/SM, register-staged tile, plain
// cached ld/st, one-barrier reduce) with the SHFL butterflies replaced by
// hardware REDUX: |x| >= 0 means the fp32 bit pattern is monotone in value,
// so absmax == bit-pattern u32 max -> __reduce_max_sync. Cuts ~200 cyc of
// serial reduce latency off each tile's load->store critical path.

constexpr int N        = 8192;
constexpr int B        = 128;
constexpr int TILES    = N / B;          // 64
constexpr int THREADS  = 512;            // 16 warps
constexpr int NWARPS   = THREADS / 32;
constexpr int SWEEPS   = B / NWARPS;     // 8 float4 per thread (32 floats)
constexpr int ROW4     = N / 4;

__device__ __forceinline__ float2 fakequant2(float a, float b) {
    // fp32 -> e5m2 (RNE, hardware cvt) -> half (exact) -> fp32 (exact)
    float2 in = make_float2(a, b);
    __nv_fp8x2_storage_t q = __nv_cvt_float2_to_fp8x2(in, __NV_SATFINITE, __NV_E5M2);
    __half2_raw hr = __nv_cvt_fp8x2_to_halfraw2(q, __NV_E5M2);
    __half2 h = *reinterpret_cast<__half2*>(&hr);
    return __half22float2(h);
}

__device__ __forceinline__ uint32_t absbits(float x) {
    return __float_as_uint(x) & 0x7fffffffu;   // |x| bit pattern; monotone for max
}

__global__ void __launch_bounds__(THREADS, 2)
quantize_tile_kernel(const float* __restrict__ x,
                     float* __restrict__ out,
                     float* __restrict__ scale_out) {
    const int tx   = blockIdx.x;          // tile col
    const int ty   = blockIdx.y;          // tile row
    const int warp = threadIdx.x >> 5;
    const int lane = threadIdx.x & 31;

    const size_t tile_base = (size_t)ty * B * N + (size_t)tx * B;
    const float4* __restrict__ xin = reinterpret_cast<const float4*>(x + tile_base);
    float4* __restrict__ oq        = reinterpret_cast<float4*>(out + tile_base);

    // ---- Load whole tile into registers; front-batched LDG.128 for MLP ----
    float4 v[SWEEPS];
    #pragma unroll
    for (int i = 0; i < SWEEPS; i++) {
        const int row = warp + i * NWARPS;
        v[i] = xin[(size_t)row * ROW4 + lane];
    }

    // ---- Local absmax as u32 bit-pattern max ----
    uint32_t am = 0u;
    #pragma unroll
    for (int i = 0; i < SWEEPS; i++) {
        am = max(am, max(max(absbits(v[i].x), absbits(v[i].y)),
                         max(absbits(v[i].z), absbits(v[i].w))));
    }

    // ---- Block reduce: REDUX warp max -> smem -> ONE barrier -> REDUX ----
    am = __reduce_max_sync(0xffffffffu, am);

    __shared__ uint32_t smax[NWARPS];
    if (lane == 0) smax[warp] = am;
    __syncthreads();
    uint32_t ab = (lane < NWARPS) ? smax[lane] : 0u;
    ab = __reduce_max_sync(0xffffffffu, ab);
    const float a = __uint_as_float(ab);

    // ---- e = ceil(log2(a)), exact; a==0 -> e=0 ----
    int e = 0;
    if (a > 0.0f) {
        int k;
        float m = frexpf(a, &k);          // a = m * 2^k, m in [0.5, 1)
        e = (m == 0.5f) ? (k - 1) : k;    // exact power of two -> k-1
    }
    const float inv = ldexpf(1.0f, 1 - e);    // 2^(MAX_EXP - e), exact

    if (threadIdx.x == 0)
        scale_out[ty * TILES + tx] = ldexpf(1.0f, e - 1);

    // ---- Quantize from registers, store ----
    #pragma unroll
    for (int i = 0; i < SWEEPS; i++) {
        const int row = warp + i * NWARPS;
        float2 xy = fakequant2(v[i].x * inv, v[i].y * inv);
        float2 zw = fakequant2(v[i].z * inv, v[i].w * inv);
        oq[(size_t)row * ROW4 + lane] = make_float4(xy.x, xy.y, zw.x, zw.y);
    }
}

extern "C" void kernel_launch(void* const* d_in, const int* in_sizes, int n_in,
                              void* d_out, int out_size) {
    (void)in_sizes; (void)n_in; (void)out_size;
    const float* x = (const float*)d_in[0];
    float* out = (float*)d_out;
    float* scale_out = out + (size_t)N * N;

    dim3 grid(TILES, TILES);
    quantize_tile_kernel<<<grid, THREADS>>>(x, out, scale_out);
}